// round 9
// baseline (speedup 1.0000x reference)
#include <cuda_runtime.h>
#include <mma.h>
#include <math.h>

using namespace nvcuda;

// Problem constants
#define HEADS   16
#define DH      64
#define BATCH   2
#define SEQ     2048
#define DMODEL  1024
#define INNER   1024
#define N3      3072
#define MROWS   (BATCH*SEQ)   // 4096

// Scratch
__device__ float g_q[BATCH*HEADS*SEQ*DH];
__device__ float g_k[BATCH*HEADS*SEQ*DH];
__device__ float g_v[BATCH*HEADS*SEQ*DH];
__device__ float g_att[MROWS*INNER];
__device__ float g_cos[SEQ*DH];
__device__ float g_sin[SEQ*DH];

__device__ __forceinline__ float to_tf32(float x) {
    float r;
    asm("cvt.rna.tf32.f32 %0, %1;" : "=f"(r) : "f"(x));
    return r;
}

// ---------------------------------------------------------------------------
// RoPE cos/sin table
// ---------------------------------------------------------------------------
__global__ void rope_table_kernel() {
    int idx = blockIdx.x * blockDim.x + threadIdx.x;
    if (idx >= SEQ * DH) return;
    int s = idx >> 6;
    int d = idx & 63;
    int f = d & 31;
    double inv = pow(10000.0, -(double)f / 32.0);
    double th  = (double)s * inv;
    g_cos[idx] = (float)cos(th);
    g_sin[idx] = (float)sin(th);
}

// ---------------------------------------------------------------------------
// TF32 wmma GEMM 1: qkv = x @ w_qkv, fused RoPE epilogue.
// CTA tile 128x64, BK=16, 256 threads (8 warps, 4x2 grid of 32x32 warp tiles).
// Dynamic smem; C staging buffer aliases A/B tiles (dead after mainloop).
// ---------------------------------------------------------------------------
#define BK 16
#define LDA 20
#define LDB 68
#define LDC 68

#define GEMM_SMEM_FLOATS (128 * LDC)   // Cs is the largest user: 8704 floats

__global__ __launch_bounds__(256) void gemm_qkv_rope(
    const float* __restrict__ A,   // x [MROWS, DMODEL]
    const float* __restrict__ Bw)  // w_qkv [DMODEL, N3]
{
    extern __shared__ __align__(32) float smq[];
    float* As = smq;                  // 128*20
    float* Bs = smq + 128 * LDA;      // 16*68
    float* Cs = smq;                  // aliases As/Bs; used after mainloop

    const int n0  = blockIdx.x * 64;
    const int m0  = blockIdx.y * 128;
    const int tid = threadIdx.x;
    const int wid = tid >> 5;
    const int wm  = (wid >> 1) * 32;  // 0,32,64,96
    const int wn  = (wid & 1) * 32;   // 0,32

    const int ar0 = tid >> 2,        ac0 = (tid & 3) * 4;   // A rows 0..63
    const int ar1 = 64 + ar0;                                // A rows 64..127
    const int br0 = tid >> 4,        bc0 = (tid & 15) * 4;  // B rows 0..15

    wmma::fragment<wmma::accumulator, 16, 16, 8, float> c[2][2];
#pragma unroll
    for (int i = 0; i < 2; i++)
#pragma unroll
        for (int j = 0; j < 2; j++)
            wmma::fill_fragment(c[i][j], 0.0f);

    float4 va0 = *(const float4*)&A[(size_t)(m0 + ar0) * DMODEL + ac0];
    float4 va1 = *(const float4*)&A[(size_t)(m0 + ar1) * DMODEL + ac0];
    float4 vb0 = *(const float4*)&Bw[(size_t)br0 * N3 + n0 + bc0];

    for (int k0 = 0; k0 < DMODEL; k0 += BK) {
        As[ar0 * LDA + ac0 + 0] = to_tf32(va0.x);
        As[ar0 * LDA + ac0 + 1] = to_tf32(va0.y);
        As[ar0 * LDA + ac0 + 2] = to_tf32(va0.z);
        As[ar0 * LDA + ac0 + 3] = to_tf32(va0.w);
        As[ar1 * LDA + ac0 + 0] = to_tf32(va1.x);
        As[ar1 * LDA + ac0 + 1] = to_tf32(va1.y);
        As[ar1 * LDA + ac0 + 2] = to_tf32(va1.z);
        As[ar1 * LDA + ac0 + 3] = to_tf32(va1.w);
        Bs[br0 * LDB + bc0 + 0] = to_tf32(vb0.x);
        Bs[br0 * LDB + bc0 + 1] = to_tf32(vb0.y);
        Bs[br0 * LDB + bc0 + 2] = to_tf32(vb0.z);
        Bs[br0 * LDB + bc0 + 3] = to_tf32(vb0.w);
        __syncthreads();

        int kn = k0 + BK;
        if (kn < DMODEL) {
            va0 = *(const float4*)&A[(size_t)(m0 + ar0) * DMODEL + kn + ac0];
            va1 = *(const float4*)&A[(size_t)(m0 + ar1) * DMODEL + kn + ac0];
            vb0 = *(const float4*)&Bw[(size_t)(kn + br0) * N3 + n0 + bc0];
        }

#pragma unroll
        for (int ks = 0; ks < 2; ks++) {
            wmma::fragment<wmma::matrix_a, 16, 16, 8, wmma::precision::tf32, wmma::row_major> a[2];
            wmma::fragment<wmma::matrix_b, 16, 16, 8, wmma::precision::tf32, wmma::row_major> b[2];
#pragma unroll
            for (int i = 0; i < 2; i++)
                wmma::load_matrix_sync(a[i], &As[(wm + i * 16) * LDA + ks * 8], LDA);
#pragma unroll
            for (int j = 0; j < 2; j++)
                wmma::load_matrix_sync(b[j], &Bs[(ks * 8) * LDB + wn + j * 16], LDB);
#pragma unroll
            for (int i = 0; i < 2; i++)
#pragma unroll
                for (int j = 0; j < 2; j++)
                    wmma::mma_sync(c[i][j], a[i], b[j], c[i][j]);
        }
        __syncthreads();
    }

    // Stage C to smem (aliases As/Bs — safe after the final barrier above)
#pragma unroll
    for (int i = 0; i < 2; i++)
#pragma unroll
        for (int j = 0; j < 2; j++)
            wmma::store_matrix_sync(&Cs[(wm + i * 16) * LDC + wn + j * 16], c[i][j],
                                    LDC, wmma::mem_row_major);
    __syncthreads();

    // Epilogue: RoPE (q,k) or copy (v), write [B,H,S,Dh]
    const int sel = n0 / INNER;
    const int h   = (n0 % INNER) / DH;
    float* dst = (sel == 0) ? g_q : (sel == 1) ? g_k : g_v;

#pragma unroll
    for (int e = 0; e < 32; e++) {
        int elem = e * 256 + tid;
        int row  = elem >> 6;      // 0..127
        int d    = elem & 63;
        int gm   = m0 + row;
        int b    = gm / SEQ;
        int s    = gm % SEQ;
        float val;
        if (sel < 2) {
            float cc = g_cos[s * DH + d];
            float sn = g_sin[s * DH + d];
            float x1 = Cs[row * LDC + d];
            float x2 = (d < 32) ? -Cs[row * LDC + d + 32] : Cs[row * LDC + d - 32];
            val = cc * x1 + sn * x2;
        } else {
            val = Cs[row * LDC + d];
        }
        dst[((size_t)(b * HEADS + h) * SEQ + s) * DH + d] = val;
    }
}

// ---------------------------------------------------------------------------
// Flash attention, TF32 wmma. Block = 64 queries x (b,h). 256 threads (8 warps).
// KV tile = 128 keys. Warp grid 4x2: S-phase splits key-cols, PV splits d-cols.
// Softmax: 4 threads per row + shfl_xor reduce (all 256 threads).
// ---------------------------------------------------------------------------
#define LDS_ 68     // K/V and O row stride
#define LDK  132    // S row stride (128 keys + pad)

#define ATTN_SMEM_FLOATS (128 * LDS_ + 64 * LDK + 64 * LDS_)

__global__ __launch_bounds__(256, 2) void attn_kernel()
{
    extern __shared__ __align__(32) float sm[];
    float* Kbuf = sm;                             // 128*68 (K, then V; Q at start)
    float* Sbuf = sm + 128 * LDS_;                // 64*132
    float* Obuf = sm + 128 * LDS_ + 64 * LDK;     // 64*68

    const int qt  = blockIdx.x;          // 0..31
    const int bh  = blockIdx.y;          // 0..31
    const int tid = threadIdx.x;
    const int wid = tid >> 5;
    const int qr0 = (wid >> 1) * 16;     // warp's 16 query rows
    const int kc0 = (wid & 1) * 64;      // warp's key-col half (S phase)
    const int dc0 = (wid & 1) * 32;      // warp's d-col half (PV phase)

    const float* qb = g_q + (size_t)bh * SEQ * DH + (size_t)qt * 64 * DH;
    const float* kb = g_k + (size_t)bh * SEQ * DH;
    const float* vb = g_v + (size_t)bh * SEQ * DH;

    // Load Q tile (scale folded) into Kbuf rows 0..63; zero Obuf.
    const float scale = 0.125f;
#pragma unroll
    for (int e = 0; e < 4; e++) {
        int v = e * 256 + tid;             // 1024 float4
        int row = v >> 4, col = (v & 15) * 4;
        float4 q4 = *(const float4*)&qb[(size_t)row * DH + col];
        Kbuf[row * LDS_ + col + 0] = to_tf32(q4.x * scale);
        Kbuf[row * LDS_ + col + 1] = to_tf32(q4.y * scale);
        Kbuf[row * LDS_ + col + 2] = to_tf32(q4.z * scale);
        Kbuf[row * LDS_ + col + 3] = to_tf32(q4.w * scale);
    }
#pragma unroll
    for (int e = 0; e < 17; e++) {
        int v = e * 256 + tid;
        if (v < 64 * LDS_) Obuf[v] = 0.0f;
    }
    __syncthreads();

    wmma::fragment<wmma::matrix_a, 16, 16, 8, wmma::precision::tf32, wmma::row_major> qf[8];
#pragma unroll
    for (int ks = 0; ks < 8; ks++)
        wmma::load_matrix_sync(qf[ks], &Kbuf[qr0 * LDS_ + ks * 8], LDS_);
    __syncthreads();   // Q reads done before K overwrites Kbuf

    // Softmax row ownership: 4 threads per row
    const int srow_i = tid >> 2;         // 0..63
    const int squad  = tid & 3;          // 0..3
    float mrow = -1e30f, lrow = 0.0f;

    for (int kt = 0; kt < SEQ / 128; kt++) {
        // ---- Load K tile: 128 keys x 64 d ----
#pragma unroll
        for (int e = 0; e < 8; e++) {
            int v = e * 256 + tid;         // 2048 float4
            int row = v >> 4, col = (v & 15) * 4;
            float4 k4 = *(const float4*)&kb[((size_t)kt * 128 + row) * DH + col];
            Kbuf[row * LDS_ + col + 0] = to_tf32(k4.x);
            Kbuf[row * LDS_ + col + 1] = to_tf32(k4.y);
            Kbuf[row * LDS_ + col + 2] = to_tf32(k4.z);
            Kbuf[row * LDS_ + col + 3] = to_tf32(k4.w);
        }
        __syncthreads();

        // ---- S = Q @ K^T : warp computes 16 rows x 64 key-cols ----
        {
            wmma::fragment<wmma::accumulator, 16, 16, 8, float> sc[4];
#pragma unroll
            for (int nf = 0; nf < 4; nf++) wmma::fill_fragment(sc[nf], 0.0f);
#pragma unroll
            for (int ks = 0; ks < 8; ks++) {
#pragma unroll
                for (int nf = 0; nf < 4; nf++) {
                    wmma::fragment<wmma::matrix_b, 16, 16, 8, wmma::precision::tf32, wmma::col_major> bf;
                    wmma::load_matrix_sync(bf, &Kbuf[(kc0 + nf * 16) * LDS_ + ks * 8], LDS_);
                    wmma::mma_sync(sc[nf], qf[ks], bf, sc[nf]);
                }
            }
#pragma unroll
            for (int nf = 0; nf < 4; nf++)
                wmma::store_matrix_sync(&Sbuf[qr0 * LDK + kc0 + nf * 16], sc[nf],
                                        LDK, wmma::mem_row_major);
        }
        __syncthreads();   // S complete; Kbuf free

        // ---- Load V tile (reuses Kbuf) ----
#pragma unroll
        for (int e = 0; e < 8; e++) {
            int v = e * 256 + tid;
            int row = v >> 4, col = (v & 15) * 4;
            float4 v4 = *(const float4*)&vb[((size_t)kt * 128 + row) * DH + col];
            Kbuf[row * LDS_ + col + 0] = to_tf32(v4.x);
            Kbuf[row * LDS_ + col + 1] = to_tf32(v4.y);
            Kbuf[row * LDS_ + col + 2] = to_tf32(v4.z);
            Kbuf[row * LDS_ + col + 3] = to_tf32(v4.w);
        }

        // ---- Online softmax: thread owns 32 cols of its row ----
        {
            float* srow = &Sbuf[srow_i * LDK + squad * 32];
            float tmax = -1e30f;
#pragma unroll 8
            for (int j = 0; j < 32; j++) tmax = fmaxf(tmax, srow[j]);
            tmax = fmaxf(tmax, __shfl_xor_sync(0xFFFFFFFF, tmax, 1));
            tmax = fmaxf(tmax, __shfl_xor_sync(0xFFFFFFFF, tmax, 2));
            float mnew = fmaxf(mrow, tmax);
            float cr   = __expf(mrow - mnew);
            float psum = 0.0f;
#pragma unroll 8
            for (int j = 0; j < 32; j++) {
                float p = __expf(srow[j] - mnew);
                psum += p;
                srow[j] = to_tf32(p);
            }
            psum += __shfl_xor_sync(0xFFFFFFFF, psum, 1);
            psum += __shfl_xor_sync(0xFFFFFFFF, psum, 2);
            lrow = lrow * cr + psum;
            mrow = mnew;
            float* orow = &Obuf[srow_i * LDS_ + squad * 16];
#pragma unroll
            for (int j = 0; j < 16; j++) orow[j] *= cr;
        }
        __syncthreads();   // P, V, rescaled O ready

        // ---- O += P @ V : warp computes 16 rows x 32 d-cols ----
        {
            wmma::fragment<wmma::accumulator, 16, 16, 8, float> oc[2];
#pragma unroll
            for (int nf = 0; nf < 2; nf++)
                wmma::load_matrix_sync(oc[nf], &Obuf[qr0 * LDS_ + dc0 + nf * 16], LDS_,
                                       wmma::mem_row_major);
#pragma unroll
            for (int ks = 0; ks < 16; ks++) {
                wmma::fragment<wmma::matrix_a, 16, 16, 8, wmma::precision::tf32, wmma::row_major> pf;
                wmma::load_matrix_sync(pf, &Sbuf[qr0 * LDK + ks * 8], LDK);
#pragma unroll
                for (int nf = 0; nf < 2; nf++) {
                    wmma::fragment<wmma::matrix_b, 16, 16, 8, wmma::precision::tf32, wmma::row_major> vf;
                    wmma::load_matrix_sync(vf, &Kbuf[(ks * 8) * LDS_ + dc0 + nf * 16], LDS_);
                    wmma::mma_sync(oc[nf], pf, vf, oc[nf]);
                }
            }
#pragma unroll
            for (int nf = 0; nf < 2; nf++)
                wmma::store_matrix_sync(&Obuf[qr0 * LDS_ + dc0 + nf * 16], oc[nf],
                                        LDS_, wmma::mem_row_major);
        }
        __syncthreads();   // PV done; Kbuf/Sbuf free next iter
    }

    // Normalize (4 threads per row, disjoint 16-col segments)
    {
        float inv = 1.0f / lrow;
        float* orow = &Obuf[srow_i * LDS_ + squad * 16];
#pragma unroll
        for (int j = 0; j < 16; j++) orow[j] *= inv;
    }
    __syncthreads();

    // Write out: g_att[(b*SEQ + s)*INNER + h*64 + d]
    const int b = bh >> 4, h = bh & 15;
#pragma unroll
    for (int e = 0; e < 4; e++) {
        int v = e * 256 + tid;             // 1024 float4
        int row = v >> 4, col4 = v & 15;
        int s = qt * 64 + row;
        float4 o4 = *(float4*)&Obuf[row * LDS_ + col4 * 4];
        *(float4*)&g_att[((size_t)(b * SEQ + s)) * INNER + h * DH + col4 * 4] = o4;
    }
}

// ---------------------------------------------------------------------------
// TF32 wmma GEMM 2: out = g_att @ w_out. CTA tile 128x64, 256 threads.
// ---------------------------------------------------------------------------
__global__ __launch_bounds__(256) void gemm_out(
    const float* __restrict__ Bw,   // w_out [INNER, DMODEL]
    float* __restrict__ C)          // out [MROWS, DMODEL]
{
    __shared__ __align__(32) float As[128 * LDA];
    __shared__ __align__(32) float Bs[BK * LDB];

    const int n0  = blockIdx.x * 64;
    const int m0  = blockIdx.y * 128;
    const int tid = threadIdx.x;
    const int wid = tid >> 5;
    const int wm  = (wid >> 1) * 32;
    const int wn  = (wid & 1) * 32;

    const int ar0 = tid >> 2,        ac0 = (tid & 3) * 4;
    const int ar1 = 64 + ar0;
    const int br0 = tid >> 4,        bc0 = (tid & 15) * 4;

    wmma::fragment<wmma::accumulator, 16, 16, 8, float> c[2][2];
#pragma unroll
    for (int i = 0; i < 2; i++)
#pragma unroll
        for (int j = 0; j < 2; j++)
            wmma::fill_fragment(c[i][j], 0.0f);

    float4 va0 = *(const float4*)&g_att[(size_t)(m0 + ar0) * INNER + ac0];
    float4 va1 = *(const float4*)&g_att[(size_t)(m0 + ar1) * INNER + ac0];
    float4 vb0 = *(const float4*)&Bw[(size_t)br0 * DMODEL + n0 + bc0];

    for (int k0 = 0; k0 < INNER; k0 += BK) {
        As[ar0 * LDA + ac0 + 0] = to_tf32(va0.x);
        As[ar0 * LDA + ac0 + 1] = to_tf32(va0.y);
        As[ar0 * LDA + ac0 + 2] = to_tf32(va0.z);
        As[ar0 * LDA + ac0 + 3] = to_tf32(va0.w);
        As[ar1 * LDA + ac0 + 0] = to_tf32(va1.x);
        As[ar1 * LDA + ac0 + 1] = to_tf32(va1.y);
        As[ar1 * LDA + ac0 + 2] = to_tf32(va1.z);
        As[ar1 * LDA + ac0 + 3] = to_tf32(va1.w);
        Bs[br0 * LDB + bc0 + 0] = to_tf32(vb0.x);
        Bs[br0 * LDB + bc0 + 1] = to_tf32(vb0.y);
        Bs[br0 * LDB + bc0 + 2] = to_tf32(vb0.z);
        Bs[br0 * LDB + bc0 + 3] = to_tf32(vb0.w);
        __syncthreads();

        int kn = k0 + BK;
        if (kn < INNER) {
            va0 = *(const float4*)&g_att[(size_t)(m0 + ar0) * INNER + kn + ac0];
            va1 = *(const float4*)&g_att[(size_t)(m0 + ar1) * INNER + kn + ac0];
            vb0 = *(const float4*)&Bw[(size_t)(kn + br0) * DMODEL + n0 + bc0];
        }

#pragma unroll
        for (int ks = 0; ks < 2; ks++) {
            wmma::fragment<wmma::matrix_a, 16, 16, 8, wmma::precision::tf32, wmma::row_major> a[2];
            wmma::fragment<wmma::matrix_b, 16, 16, 8, wmma::precision::tf32, wmma::row_major> b[2];
#pragma unroll
            for (int i = 0; i < 2; i++)
                wmma::load_matrix_sync(a[i], &As[(wm + i * 16) * LDA + ks * 8], LDA);
#pragma unroll
            for (int j = 0; j < 2; j++)
                wmma::load_matrix_sync(b[j], &Bs[(ks * 8) * LDB + wn + j * 16], LDB);
#pragma unroll
            for (int i = 0; i < 2; i++)
#pragma unroll
                for (int j = 0; j < 2; j++)
                    wmma::mma_sync(c[i][j], a[i], b[j], c[i][j]);
        }
        __syncthreads();
    }

#pragma unroll
    for (int i = 0; i < 2; i++)
#pragma unroll
        for (int j = 0; j < 2; j++)
            wmma::store_matrix_sync(&C[(size_t)(m0 + wm + i * 16) * DMODEL + n0 + wn + j * 16],
                                    c[i][j], DMODEL, wmma::mem_row_major);
}

// ---------------------------------------------------------------------------
extern "C" void kernel_launch(void* const* d_in, const int* in_sizes, int n_in,
                              void* d_out, int out_size)
{
    const float* x     = (const float*)d_in[0];
    const float* w_qkv = (const float*)d_in[1];
    const float* w_out = (const float*)d_in[2];
    float* out = (float*)d_out;

    cudaFuncSetAttribute(attn_kernel,
                         cudaFuncAttributeMaxDynamicSharedMemorySize,
                         ATTN_SMEM_FLOATS * sizeof(float));
    cudaFuncSetAttribute(gemm_qkv_rope,
                         cudaFuncAttributeMaxDynamicSharedMemorySize,
                         GEMM_SMEM_FLOATS * sizeof(float));

    rope_table_kernel<<<(SEQ * DH + 255) / 256, 256>>>();
    gemm_qkv_rope<<<dim3(N3 / 64, MROWS / 128), 256,
                    GEMM_SMEM_FLOATS * sizeof(float)>>>(x, w_qkv);
    attn_kernel<<<dim3(SEQ / 64, BATCH * HEADS), 256,
                  ATTN_SMEM_FLOATS * sizeof(float)>>>();
    gemm_out<<<dim3(DMODEL / 64, MROWS / 128), 256>>>(w_out, out);
}